// round 6
// baseline (speedup 1.0000x reference)
#include <cuda_runtime.h>
#include <cuda_bf16.h>
#include <cstdint>

// ---------------------------------------------------------------------------
// KAN 3-layer (12->64->64->24) via warp mma.sync bf16 3-pass (hi/lo split).
// 256 threads / 128 rows per CTA. Pipelined; feature scatter uses static
// 9-value vectors + paired bf16x2 stores (no zero pass, ~10 stores/task).
// ---------------------------------------------------------------------------

#define MAXN (32 * 64 * 64)

__device__ float g_h1[64 * MAXN];
__device__ float g_h2[64 * MAXN];
__device__ __align__(16) __nv_bfloat16 g_Whi0[64 * 128];
__device__ __align__(16) __nv_bfloat16 g_Wlo0[64 * 128];
__device__ __align__(16) __nv_bfloat16 g_Whi1[64 * 576];
__device__ __align__(16) __nv_bfloat16 g_Wlo1[64 * 576];
__device__ __align__(16) __nv_bfloat16 g_Whi2[24 * 576];
__device__ __align__(16) __nv_bfloat16 g_Wlo2[24 * 576];

// ------------------------------- helpers -----------------------------------

__device__ __forceinline__ uint32_t smem_u32(const void* p) {
    uint32_t a;
    asm("{ .reg .u64 t; cvta.to.shared.u64 t, %1; cvt.u32.u64 %0, t; }"
        : "=r"(a) : "l"(p));
    return a;
}
__device__ __forceinline__ uint32_t sw128(uint32_t off) {
    return off ^ ((off >> 3) & 0x70);
}
__device__ __forceinline__ void ldsm4(uint32_t addr, uint32_t r[4]) {
    asm volatile("ldmatrix.sync.aligned.m8n8.x4.shared.b16 {%0,%1,%2,%3}, [%4];"
                 : "=r"(r[0]), "=r"(r[1]), "=r"(r[2]), "=r"(r[3]) : "r"(addr));
}
__device__ __forceinline__ void ldsm2(uint32_t addr, uint32_t r[2]) {
    asm volatile("ldmatrix.sync.aligned.m8n8.x2.shared.b16 {%0,%1}, [%2];"
                 : "=r"(r[0]), "=r"(r[1]) : "r"(addr));
}
__device__ __forceinline__ void mma16816(float c[4], const uint32_t a[4],
                                         uint32_t b0, uint32_t b1) {
    asm volatile(
        "mma.sync.aligned.m16n8k16.row.col.f32.bf16.bf16.f32 "
        "{%0,%1,%2,%3},{%4,%5,%6,%7},{%8,%9},{%0,%1,%2,%3};"
        : "+f"(c[0]), "+f"(c[1]), "+f"(c[2]), "+f"(c[3])
        : "r"(a[0]), "r"(a[1]), "r"(a[2]), "r"(a[3]), "r"(b0), "r"(b1));
}
__device__ __forceinline__ void sts16(uint32_t addr, unsigned short v) {
    asm volatile("st.shared.b16 [%0], %1;" :: "r"(addr), "h"(v));
}
__device__ __forceinline__ void sts32(uint32_t addr, uint32_t v) {
    asm volatile("st.shared.b32 [%0], %1;" :: "r"(addr), "r"(v));
}
__device__ __forceinline__ void cp16(uint32_t dst, const void* src) {
    asm volatile("cp.async.ca.shared.global [%0], [%1], 16;"
                 :: "r"(dst), "l"(src) : "memory");
}
__device__ __forceinline__ void cp_commit() {
    asm volatile("cp.async.commit_group;" ::: "memory");
}
__device__ __forceinline__ void cp_wait0() {
    asm volatile("cp.async.wait_group 0;" ::: "memory");
}
__device__ __forceinline__ void split_hl(float v, unsigned short& h, unsigned short& l) {
    __nv_bfloat16 hb = __float2bfloat16(v);
    float hf = __bfloat162float(hb);
    __nv_bfloat16 lb = __float2bfloat16(v - hf);
    h = __bfloat16_as_ushort(hb);
    l = __bfloat16_as_ushort(lb);
}
// pack (a,b) -> hi bf16x2 + lo bf16x2 (residuals); a in low half
__device__ __forceinline__ void split_pair(float a, float b, uint32_t& hp, uint32_t& lp) {
    __nv_bfloat162 h2 = __floats2bfloat162_rn(a, b);
    hp = *reinterpret_cast<uint32_t*>(&h2);
    float ha = __bfloat162float(__low2bfloat16(h2));
    float hb = __bfloat162float(__high2bfloat16(h2));
    __nv_bfloat162 l2 = __floats2bfloat162_rn(a - ha, b - hb);
    lp = *reinterpret_cast<uint32_t*>(&l2);
}

// ------------------------------- fold kernel -------------------------------
__global__ void fold_hilo(const float* __restrict__ coef, const float* __restrict__ sbp,
                          const float* __restrict__ ss, __nv_bfloat16* __restrict__ Whi,
                          __nv_bfloat16* __restrict__ Wlo, int IN, int OUT, int KPAD) {
    int idx = blockIdx.x * blockDim.x + threadIdx.x;
    if (idx >= OUT * KPAD) return;
    int o = idx / KPAD, k = idx % KPAD;
    float w = 0.0f;
    if (k < IN * 9) {
        int i = k / 9, j = k % 9;
        w = (j == 0) ? sbp[i * OUT + o] : coef[(i * OUT + o) * 8 + (j - 1)] * ss[i * OUT + o];
    }
    __nv_bfloat16 hi = __float2bfloat16(w);
    __nv_bfloat16 lo = __float2bfloat16(w - __bfloat162float(hi));
    Whi[idx] = hi;
    Wlo[idx] = lo;
}

// ------------------------------- layer kernel ------------------------------
template <int IN, int OUT, int K, int KPAD, int NCHUNK, bool IN_NCHW, bool OUT_NCHW>
__global__ void __launch_bounds__(256, 2)
kan_mma(const float* __restrict__ hin, const float* __restrict__ grid,
        const __nv_bfloat16* __restrict__ Whi, const __nv_bfloat16* __restrict__ Wlo,
        float* __restrict__ hout, int N) {
    constexpr int NT = OUT / 8;
    constexpr int NT2 = NT / 2;
    constexpr int ABUF = 128 * 128;  // 16KB per A buffer
    constexpr int BBUF = OUT * 128;

    extern __shared__ char dsm[];
    const uint32_t sb = smem_u32(dsm);
    const uint32_t BBASE = sb + 4 * ABUF;

    const int tid = threadIdx.x;
    const int wid = tid >> 5;
    const int lane = tid & 31;
    const int row0 = blockIdx.x * 128;

    const float t0 = __ldg(grid + 0);
    const float invh = 1.0f / (__ldg(grid + 1) - t0);
    const float t11 = __ldg(grid + 11);

    const int r = tid & 127;
    const int half = tid >> 7;
    const int rowg = row0 + r;
    const int img = rowg >> 12;
    const int pix = rowg & 4095;
    const uint32_t rbase = (uint32_t)(r * 128);

    // ldmatrix fragment addressing
    const int gq = lane >> 3;
    const uint32_t a_base =
        (uint32_t)((wid * 16 + (lane & 7) + 8 * (gq & 1)) * 128 + (gq >> 1) * 16);
    const int brow = (lane & 7) + 8 * (gq >> 1);
    const int bseg = gq & 1;

    float acc[NT][4];
#pragma unroll
    for (int p = 0; p < NT; p++)
#pragma unroll
        for (int q = 0; q < 4; q++) acc[p][q] = 0.0f;

    // ---------------- pipeline helpers ----------------
    auto prefetch = [&](int c, float* xr) {
        const int klo = c * 64;
        const int ilo = klo / 9;
        int ihi = (klo + 63) / 9;
        if (ihi > IN - 1) ihi = IN - 1;
#pragma unroll
        for (int q = 0; q < 5; q++) {
            int i = ilo + half + 2 * q;
            int idx;
            if (IN_NCHW) idx = (img * IN + i) * 4096 + pix;
            else idx = i * N + rowg;
            xr[q] = (i <= ihi) ? __ldg(hin + idx) : 0.0f;
        }
    };

    auto stageB = [&](int c, int st) {
        uint32_t bb = BBASE + (uint32_t)(st * 2) * BBUF;
        for (int v = tid; v < OUT * 16; v += 256) {
            int h = v >= OUT * 8;
            int u = v - (h ? OUT * 8 : 0);
            int o = u >> 3, seg = u & 7;
            const __nv_bfloat16* src = (h ? Wlo : Whi) + o * KPAD + c * 64 + seg * 8;
            cp16(bb + (uint32_t)h * BBUF + sw128((uint32_t)(o * 128 + seg * 16)), src);
        }
        cp_commit();
    };

    auto scatter = [&](int c, int st, const float* xr) {
        const uint32_t ah = sb + (uint32_t)(st * 2) * ABUF;
        const int klo = c * 64;
        const int ilo = klo / 9;
        int ihi = (klo + 63) / 9;
        if (ihi > IN - 1) ihi = IN - 1;
#pragma unroll
        for (int q = 0; q < 5; q++) {
            int i = ilo + half + 2 * q;
            if (i > ihi) break;
            float x = xr[q];
            float f0 = __fdividef(x, 1.0f + __expf(-x));  // silu

            bool inr = (x >= t0) && (x < t11);
            float s = (x - t0) * invh;
            s = fminf(fmaxf(s, 0.0f), 10.999f);
            int m = (int)s;
            float u1 = s - (float)m;
            float um = 1.0f - u1;
            float u2 = u1 * u1, u3 = u2 * u1;
            float fl = inr ? (1.0f / 6.0f) : 0.0f;
            float v0 = um * um * um * fl;
            float v1 = (3.0f * u3 - 6.0f * u2 + 4.0f) * fl;
            float v2 = (-3.0f * u3 + 3.0f * u2 + 3.0f * u1 + 1.0f) * fl;
            float v3 = u3 * fl;

            // static 9-value vector: val[0]=silu, val[j]=basis j-1
            float val[9];
            val[0] = f0;
#pragma unroll
            for (int j = 1; j < 9; j++) {
                int g = j + 2 - m;  // (j-1) - (m-3)
                val[j] = (g == 0) ? v0 : (g == 1) ? v1 : (g == 2) ? v2
                         : (g == 3) ? v3 : 0.0f;
            }

            const int kb = i * 9 - klo;  // warp-uniform
            if (kb >= 0 && kb <= 55) {
                // fast path: full window in-range; paired stores
                if ((kb & 1) == 0) {
#pragma unroll
                    for (int t = 0; t < 4; t++) {
                        uint32_t hp, lp;
                        split_pair(val[2 * t], val[2 * t + 1], hp, lp);
                        uint32_t off = sw128(rbase + (uint32_t)((kb + 2 * t) * 2));
                        sts32(ah + off, hp);
                        sts32(ah + ABUF + off, lp);
                    }
                    unsigned short hh, ll;
                    split_hl(val[8], hh, ll);
                    uint32_t off = sw128(rbase + (uint32_t)((kb + 8) * 2));
                    sts16(ah + off, hh);
                    sts16(ah + ABUF + off, ll);
                } else {
                    unsigned short hh, ll;
                    split_hl(val[0], hh, ll);
                    uint32_t off = sw128(rbase + (uint32_t)(kb * 2));
                    sts16(ah + off, hh);
                    sts16(ah + ABUF + off, ll);
#pragma unroll
                    for (int t = 0; t < 4; t++) {
                        uint32_t hp, lp;
                        split_pair(val[1 + 2 * t], val[2 + 2 * t], hp, lp);
                        uint32_t o2 = sw128(rbase + (uint32_t)((kb + 1 + 2 * t) * 2));
                        sts32(ah + o2, hp);
                        sts32(ah + ABUF + o2, lp);
                    }
                }
            } else {
                // boundary: predicated per-slot stores
#pragma unroll
                for (int j = 0; j < 9; j++) {
                    int k = kb + j;
                    if ((unsigned)k < 64u) {
                        unsigned short hh, ll;
                        split_hl(val[j], hh, ll);
                        uint32_t off = sw128(rbase + (uint32_t)(k * 2));
                        sts16(ah + off, hh);
                        sts16(ah + ABUF + off, ll);
                    }
                }
            }
        }
        // tail zero for layer0 last chunk (cols K-klo .. 63 never covered)
        if (K < KPAD && c == NCHUNK - 1) {
            constexpr int PADC = 64 - (K & 63);  // 20 for K=108
            int base = 64 - PADC + (PADC / 2) * half;
#pragma unroll
            for (int j = 0; j < PADC / 4; j++) {  // pairs (PADC/2 cols per half)
                uint32_t off = sw128(rbase + (uint32_t)((base + 2 * j) * 2));
                sts32(ah + off, 0);
                sts32(ah + ABUF + off, 0);
            }
        }
    };

    auto mma_chunk = [&](int st) {
        const uint32_t Ah = sb + (uint32_t)(st * 2) * ABUF;
        const uint32_t Al = Ah + ABUF;
        const uint32_t Bh = BBASE + (uint32_t)(st * 2) * BBUF;
        const uint32_t Bl = Bh + BBUF;
#pragma unroll
        for (int ks = 0; ks < 4; ks++) {
            uint32_t asw = sw128(a_base + (uint32_t)(ks * 32));
            uint32_t ah[4], al[4];
            ldsm4(Ah + asw, ah);
            ldsm4(Al + asw, al);
#pragma unroll
            for (int q = 0; q < NT2; q++) {
                uint32_t bo = sw128((uint32_t)((16 * q + brow) * 128 + bseg * 16 + ks * 32));
                uint32_t bh[4], bl[4];
                ldsm4(Bh + bo, bh);
                ldsm4(Bl + bo, bl);
                mma16816(acc[2 * q], ah, bh[0], bh[1]);
                mma16816(acc[2 * q + 1], ah, bh[2], bh[3]);
                mma16816(acc[2 * q], ah, bl[0], bl[1]);
                mma16816(acc[2 * q + 1], ah, bl[2], bl[3]);
                mma16816(acc[2 * q], al, bh[0], bh[1]);
                mma16816(acc[2 * q + 1], al, bh[2], bh[3]);
            }
            if constexpr (NT & 1) {
                uint32_t bo = sw128((uint32_t)((8 * (NT - 1) + (lane & 7)) * 128 +
                                               ((lane >> 3) & 1) * 16 + ks * 32));
                uint32_t bh2[2], bl2[2];
                ldsm2(Bh + bo, bh2);
                ldsm2(Bl + bo, bl2);
                mma16816(acc[NT - 1], ah, bh2[0], bh2[1]);
                mma16816(acc[NT - 1], ah, bl2[0], bl2[1]);
                mma16816(acc[NT - 1], al, bh2[0], bh2[1]);
            }
        }
    };

    // ---------------- main pipeline ----------------
    float xb0[5], xb1[5];
    prefetch(0, xb0);
    if (NCHUNK > 1) prefetch(1, xb1);
    stageB(0, 0);
    scatter(0, 0, xb0);
    cp_wait0();
    __syncthreads();

    for (int c = 0; c < NCHUNK; c++) {
        const int st = c & 1;
        if (c + 2 < NCHUNK) prefetch(c + 2, (c & 1) ? xb1 : xb0);
        if (c + 1 < NCHUNK) stageB(c + 1, st ^ 1);
        mma_chunk(st);
        if (c + 1 < NCHUNK) scatter(c + 1, st ^ 1, ((c + 1) & 1) ? xb1 : xb0);
        cp_wait0();
        __syncthreads();
    }

    // ---------------- epilogue: smem transpose -> coalesced STG ----------------
    constexpr int SP = 132;
    float* S = reinterpret_cast<float*>(dsm);  // reuse A region
    {
        const int er0 = wid * 16 + (lane >> 2);
        const int er1 = er0 + 8;
#pragma unroll
        for (int p = 0; p < NT; p++) {
            int o = p * 8 + (lane & 3) * 2;
            S[o * SP + er0] = acc[p][0];
            S[(o + 1) * SP + er0] = acc[p][1];
            S[o * SP + er1] = acc[p][2];
            S[(o + 1) * SP + er1] = acc[p][3];
        }
    }
    __syncthreads();
    for (int idx = tid; idx < OUT * 128; idx += 256) {
        int o = idx >> 7;
        int rr = idx & 127;
        float val = S[o * SP + rr];
        if (OUT_NCHW) hout[((row0 >> 12) * OUT + o) * 4096 + (row0 & 4095) + rr] = val;
        else hout[o * N + row0 + rr] = val;
    }
}

// ------------------------------- launch ------------------------------------

extern "C" void kernel_launch(void* const* d_in, const int* in_sizes, int n_in,
                              void* d_out, int out_size) {
    const float* x     = (const float*)d_in[0];
    const float* grid0 = (const float*)d_in[1];
    const float* coef0 = (const float*)d_in[2];
    const float* sb0   = (const float*)d_in[3];
    const float* ss0   = (const float*)d_in[4];
    const float* grid1 = (const float*)d_in[5];
    const float* coef1 = (const float*)d_in[6];
    const float* sb1   = (const float*)d_in[7];
    const float* ss1   = (const float*)d_in[8];
    const float* grid2 = (const float*)d_in[9];
    const float* coef2 = (const float*)d_in[10];
    const float* sb2   = (const float*)d_in[11];
    const float* ss2   = (const float*)d_in[12];
    float* out = (float*)d_out;

    int N = in_sizes[0] / 12;
    if (N > MAXN) N = MAXN;

    float *h1, *h2;
    __nv_bfloat16 *Whi0, *Wlo0, *Whi1, *Wlo1, *Whi2, *Wlo2;
    cudaGetSymbolAddress((void**)&h1, g_h1);
    cudaGetSymbolAddress((void**)&h2, g_h2);
    cudaGetSymbolAddress((void**)&Whi0, g_Whi0);
    cudaGetSymbolAddress((void**)&Wlo0, g_Wlo0);
    cudaGetSymbolAddress((void**)&Whi1, g_Whi1);
    cudaGetSymbolAddress((void**)&Wlo1, g_Wlo1);
    cudaGetSymbolAddress((void**)&Whi2, g_Whi2);
    cudaGetSymbolAddress((void**)&Wlo2, g_Wlo2);

    fold_hilo<<<(64 * 128 + 255) / 256, 256>>>(coef0, sb0, ss0, Whi0, Wlo0, 12, 64, 128);
    fold_hilo<<<(64 * 576 + 255) / 256, 256>>>(coef1, sb1, ss1, Whi1, Wlo1, 64, 64, 576);
    fold_hilo<<<(24 * 576 + 255) / 256, 256>>>(coef2, sb2, ss2, Whi2, Wlo2, 64, 24, 576);

    auto k0 = kan_mma<12, 64, 108, 128, 2, true, false>;
    auto k1 = kan_mma<64, 64, 576, 576, 9, false, false>;
    auto k2 = kan_mma<64, 24, 576, 576, 9, false, true>;

    constexpr int SM01 = 4 * 128 * 128 + 4 * 64 * 128;  // 98304
    constexpr int SM2  = 4 * 128 * 128 + 4 * 24 * 128;  // 77824
    cudaFuncSetAttribute(k0, cudaFuncAttributeMaxDynamicSharedMemorySize, SM01);
    cudaFuncSetAttribute(k1, cudaFuncAttributeMaxDynamicSharedMemorySize, SM01);
    cudaFuncSetAttribute(k2, cudaFuncAttributeMaxDynamicSharedMemorySize, SM2);

    int blocks = N / 128;
    k0<<<blocks, 256, SM01>>>(x, grid0, Whi0, Wlo0, h1, N);
    k1<<<blocks, 256, SM01>>>(h1, grid1, Whi1, Wlo1, h2, N);
    k2<<<blocks, 256, SM2>>>(h2, grid2, Whi2, Wlo2, out, N);
}

// round 7
// speedup vs baseline: 1.8989x; 1.8989x over previous
#include <cuda_runtime.h>
#include <cuda_bf16.h>
#include <cstdint>

// ---------------------------------------------------------------------------
// KAN 3-layer (12->64->64->24) via warp mma.sync bf16 3-pass (hi/lo split).
// 256 threads / 128 rows per CTA. A stored K-major (conflict-free scatter
// stores + ldmatrix.trans); B via cp.async; ping-pong; 1 barrier/chunk.
// ---------------------------------------------------------------------------

#define MAXN (32 * 64 * 64)

__device__ float g_h1[64 * MAXN];
__device__ float g_h2[64 * MAXN];
__device__ __align__(16) __nv_bfloat16 g_Whi0[64 * 128];
__device__ __align__(16) __nv_bfloat16 g_Wlo0[64 * 128];
__device__ __align__(16) __nv_bfloat16 g_Whi1[64 * 576];
__device__ __align__(16) __nv_bfloat16 g_Wlo1[64 * 576];
__device__ __align__(16) __nv_bfloat16 g_Whi2[24 * 576];
__device__ __align__(16) __nv_bfloat16 g_Wlo2[24 * 576];

// ------------------------------- helpers -----------------------------------

__device__ __forceinline__ uint32_t smem_u32(const void* p) {
    uint32_t a;
    asm("{ .reg .u64 t; cvta.to.shared.u64 t, %1; cvt.u32.u64 %0, t; }"
        : "=r"(a) : "l"(p));
    return a;
}
__device__ __forceinline__ uint32_t sw128(uint32_t off) {
    return off ^ ((off >> 3) & 0x70);
}
// K-major A tile: AT[k][m], 256B per k-row, per-k XOR swizzle in 128B halves
__device__ __forceinline__ uint32_t swAT(int k, int m) {
    uint32_t off = (uint32_t)(m * 2);
    return (uint32_t)(k * 256) + (off & 0x80u) +
           ((off & 0x7Fu) ^ (((uint32_t)k & 7u) << 4));
}
__device__ __forceinline__ void ldsm4(uint32_t addr, uint32_t r[4]) {
    asm volatile("ldmatrix.sync.aligned.m8n8.x4.shared.b16 {%0,%1,%2,%3}, [%4];"
                 : "=r"(r[0]), "=r"(r[1]), "=r"(r[2]), "=r"(r[3]) : "r"(addr));
}
__device__ __forceinline__ void ldsm4t(uint32_t addr, uint32_t r[4]) {
    asm volatile("ldmatrix.sync.aligned.m8n8.x4.trans.shared.b16 {%0,%1,%2,%3}, [%4];"
                 : "=r"(r[0]), "=r"(r[1]), "=r"(r[2]), "=r"(r[3]) : "r"(addr));
}
__device__ __forceinline__ void ldsm2(uint32_t addr, uint32_t r[2]) {
    asm volatile("ldmatrix.sync.aligned.m8n8.x2.shared.b16 {%0,%1}, [%2];"
                 : "=r"(r[0]), "=r"(r[1]) : "r"(addr));
}
__device__ __forceinline__ void mma16816(float c[4], const uint32_t a[4],
                                         uint32_t b0, uint32_t b1) {
    asm volatile(
        "mma.sync.aligned.m16n8k16.row.col.f32.bf16.bf16.f32 "
        "{%0,%1,%2,%3},{%4,%5,%6,%7},{%8,%9},{%0,%1,%2,%3};"
        : "+f"(c[0]), "+f"(c[1]), "+f"(c[2]), "+f"(c[3])
        : "r"(a[0]), "r"(a[1]), "r"(a[2]), "r"(a[3]), "r"(b0), "r"(b1));
}
__device__ __forceinline__ void sts16(uint32_t addr, unsigned short v) {
    asm volatile("st.shared.b16 [%0], %1;" :: "r"(addr), "h"(v));
}
__device__ __forceinline__ void cp16(uint32_t dst, const void* src) {
    asm volatile("cp.async.ca.shared.global [%0], [%1], 16;"
                 :: "r"(dst), "l"(src) : "memory");
}
__device__ __forceinline__ void cp_commit() {
    asm volatile("cp.async.commit_group;" ::: "memory");
}
__device__ __forceinline__ void cp_wait0() {
    asm volatile("cp.async.wait_group 0;" ::: "memory");
}
__device__ __forceinline__ void split_hl(float v, unsigned short& h, unsigned short& l) {
    __nv_bfloat16 hb = __float2bfloat16(v);
    float hf = __bfloat162float(hb);
    __nv_bfloat16 lb = __float2bfloat16(v - hf);
    h = __bfloat16_as_ushort(hb);
    l = __bfloat16_as_ushort(lb);
}

// ------------------------------- fold kernel -------------------------------
__global__ void fold_hilo(const float* __restrict__ coef, const float* __restrict__ sbp,
                          const float* __restrict__ ss, __nv_bfloat16* __restrict__ Whi,
                          __nv_bfloat16* __restrict__ Wlo, int IN, int OUT, int KPAD) {
    int idx = blockIdx.x * blockDim.x + threadIdx.x;
    if (idx >= OUT * KPAD) return;
    int o = idx / KPAD, k = idx % KPAD;
    float w = 0.0f;
    if (k < IN * 9) {
        int i = k / 9, j = k % 9;
        w = (j == 0) ? sbp[i * OUT + o] : coef[(i * OUT + o) * 8 + (j - 1)] * ss[i * OUT + o];
    }
    __nv_bfloat16 hi = __float2bfloat16(w);
    __nv_bfloat16 lo = __float2bfloat16(w - __bfloat162float(hi));
    Whi[idx] = hi;
    Wlo[idx] = lo;
}

// ------------------------------- layer kernel ------------------------------
template <int IN, int OUT, int K, int KPAD, int NCHUNK, bool IN_NCHW, bool OUT_NCHW>
__global__ void __launch_bounds__(256, 2)
kan_mma(const float* __restrict__ hin, const float* __restrict__ grid,
        const __nv_bfloat16* __restrict__ Whi, const __nv_bfloat16* __restrict__ Wlo,
        float* __restrict__ hout, int N) {
    constexpr int NT = OUT / 8;
    constexpr int NT2 = NT / 2;
    constexpr int ABUF = 64 * 256;   // 16KB per A buffer (K-major: 64 k x 128 m x 2B)
    constexpr int BBUF = OUT * 128;

    extern __shared__ char dsm[];
    const uint32_t sb = smem_u32(dsm);
    const uint32_t BBASE = sb + 4 * ABUF;

    const int tid = threadIdx.x;
    const int wid = tid >> 5;
    const int lane = tid & 31;
    const int row0 = blockIdx.x * 128;

    const float t0 = __ldg(grid + 0);
    const float invh = 1.0f / (__ldg(grid + 1) - t0);
    const float t11 = __ldg(grid + 11);

    const int r = tid & 127;
    const int half = tid >> 7;
    const int rowg = row0 + r;
    const int img = rowg >> 12;
    const int pix = rowg & 4095;

    // fragment addressing
    const int gq = lane >> 3;
    const int a_k = (lane & 7) + ((gq >> 1) * 8);
    const int a_m = wid * 16 + (gq & 1) * 8;
    const uint32_t a_sw = swAT(a_k, a_m);  // +ks*4096 per k-step
    const int brow = (lane & 7) + 8 * (gq >> 1);
    const int bseg = gq & 1;

    float acc[NT][4];
#pragma unroll
    for (int p = 0; p < NT; p++)
#pragma unroll
        for (int q = 0; q < 4; q++) acc[p][q] = 0.0f;

    // ---------------- pipeline helpers ----------------
    auto prefetch = [&](int c, float* xr) {
        const int klo = c * 64;
        const int ilo = klo / 9;
        int ihi = (klo + 63) / 9;
        if (ihi > IN - 1) ihi = IN - 1;
#pragma unroll
        for (int q = 0; q < 5; q++) {
            int i = ilo + half + 2 * q;
            int idx;
            if (IN_NCHW) idx = (img * IN + i) * 4096 + pix;
            else idx = i * N + rowg;
            xr[q] = (i <= ihi) ? __ldg(hin + idx) : 0.0f;
        }
    };

    auto stageB = [&](int c, int st) {
        uint32_t bb = BBASE + (uint32_t)(st * 2) * BBUF;
        for (int v = tid; v < OUT * 16; v += 256) {
            int h = v >= OUT * 8;
            int u = v - (h ? OUT * 8 : 0);
            int o = u >> 3, seg = u & 7;
            const __nv_bfloat16* src = (h ? Wlo : Whi) + o * KPAD + c * 64 + seg * 8;
            cp16(bb + (uint32_t)h * BBUF + sw128((uint32_t)(o * 128 + seg * 16)), src);
        }
        cp_commit();
    };

    auto scatter = [&](int c, int st, const float* xr) {
        const uint32_t ah = sb + (uint32_t)(st * 2) * ABUF;
        const int klo = c * 64;
        const int ilo = klo / 9;
        int ihi = (klo + 63) / 9;
        if (ihi > IN - 1) ihi = IN - 1;
#pragma unroll
        for (int q = 0; q < 5; q++) {
            int i = ilo + half + 2 * q;
            if (i > ihi) break;
            float x = xr[q];
            float f0 = __fdividef(x, 1.0f + __expf(-x));  // silu

            bool inr = (x >= t0) && (x < t11);
            float s = (x - t0) * invh;
            s = fminf(fmaxf(s, 0.0f), 10.999f);
            int m = (int)s;
            float u1 = s - (float)m;
            float um = 1.0f - u1;
            float u2 = u1 * u1, u3 = u2 * u1;
            float fl = inr ? (1.0f / 6.0f) : 0.0f;
            float v0 = um * um * um * fl;
            float v1 = (3.0f * u3 - 6.0f * u2 + 4.0f) * fl;
            float v2 = (-3.0f * u3 + 3.0f * u2 + 3.0f * u1 + 1.0f) * fl;
            float v3 = u3 * fl;

            const int kb = i * 9 - klo;
            // zero basis slots (j=1..8); each store is warp-contiguous
#pragma unroll
            for (int j = 1; j < 9; j++) {
                int k = kb + j;
                if ((unsigned)k < 64u) {
                    uint32_t off = swAT(k, r);
                    sts16(ah + off, 0);
                    sts16(ah + ABUF + off, 0);
                }
            }
            unsigned short hh, ll;
            if ((unsigned)kb < 64u) {  // silu slot
                split_hl(f0, hh, ll);
                uint32_t off = swAT(kb, r);
                sts16(ah + off, hh);
                sts16(ah + ABUF + off, ll);
            }
            const int kw = kb + m - 2;  // k for g=0
#pragma unroll
            for (int g = 0; g < 4; g++) {
                int bi = m - 3 + g;
                int k = kw + g;
                float v = (g == 0) ? v0 : (g == 1) ? v1 : (g == 2) ? v2 : v3;
                if ((unsigned)bi <= 7u && (unsigned)k < 64u) {
                    split_hl(v, hh, ll);
                    uint32_t off = swAT(k, r);
                    sts16(ah + off, hh);
                    sts16(ah + ABUF + off, ll);
                }
            }
        }
        // tail zero for layer0 last chunk (cols K-klo .. 63 never covered)
        if (K < KPAD && c == NCHUNK - 1) {
            constexpr int PADC = 64 - (K & 63);  // 20 for K=108
            int base = 64 - PADC + (PADC / 2) * half;
#pragma unroll
            for (int j = 0; j < PADC / 2; j++) {
                uint32_t off = swAT(base + j, r);
                sts16(ah + off, 0);
                sts16(ah + ABUF + off, 0);
            }
        }
    };

    auto mma_chunk = [&](int st) {
        const uint32_t Ah = sb + (uint32_t)(st * 2) * ABUF;
        const uint32_t Al = Ah + ABUF;
        const uint32_t Bh = BBASE + (uint32_t)(st * 2) * BBUF;
        const uint32_t Bl = Bh + BBUF;
#pragma unroll
        for (int ks = 0; ks < 4; ks++) {
            uint32_t aoff = a_sw + (uint32_t)(ks * 4096);  // 16 k-rows * 256B
            uint32_t ah[4], al[4];
            ldsm4t(Ah + aoff, ah);
            ldsm4t(Al + aoff, al);
#pragma unroll
            for (int q = 0; q < NT2; q++) {
                uint32_t bo = sw128((uint32_t)((16 * q + brow) * 128 + bseg * 16 + ks * 32));
                uint32_t bh[4], bl[4];
                ldsm4(Bh + bo, bh);
                ldsm4(Bl + bo, bl);
                mma16816(acc[2 * q], ah, bh[0], bh[1]);
                mma16816(acc[2 * q + 1], ah, bh[2], bh[3]);
                mma16816(acc[2 * q], ah, bl[0], bl[1]);
                mma16816(acc[2 * q + 1], ah, bl[2], bl[3]);
                mma16816(acc[2 * q], al, bh[0], bh[1]);
                mma16816(acc[2 * q + 1], al, bh[2], bh[3]);
            }
            if constexpr (NT & 1) {
                uint32_t bo = sw128((uint32_t)((8 * (NT - 1) + (lane & 7)) * 128 +
                                               ((lane >> 3) & 1) * 16 + ks * 32));
                uint32_t bh2[2], bl2[2];
                ldsm2(Bh + bo, bh2);
                ldsm2(Bl + bo, bl2);
                mma16816(acc[NT - 1], ah, bh2[0], bh2[1]);
                mma16816(acc[NT - 1], ah, bl2[0], bl2[1]);
                mma16816(acc[NT - 1], al, bh2[0], bh2[1]);
            }
        }
    };

    // ---------------- main pipeline ----------------
    float xb0[5], xb1[5];
    prefetch(0, xb0);
    if (NCHUNK > 1) prefetch(1, xb1);
    stageB(0, 0);
    scatter(0, 0, xb0);
    cp_wait0();
    __syncthreads();

    for (int c = 0; c < NCHUNK; c++) {
        const int st = c & 1;
        if (c + 2 < NCHUNK) prefetch(c + 2, (c & 1) ? xb1 : xb0);
        if (c + 1 < NCHUNK) stageB(c + 1, st ^ 1);
        mma_chunk(st);
        if (c + 1 < NCHUNK) scatter(c + 1, st ^ 1, ((c + 1) & 1) ? xb1 : xb0);
        cp_wait0();
        __syncthreads();
    }

    // ---------------- epilogue: smem transpose -> coalesced STG ----------------
    constexpr int SP = 132;
    float* S = reinterpret_cast<float*>(dsm);  // reuse A region
    __syncthreads();
    {
        const int er0 = wid * 16 + (lane >> 2);
        const int er1 = er0 + 8;
#pragma unroll
        for (int p = 0; p < NT; p++) {
            int o = p * 8 + (lane & 3) * 2;
            S[o * SP + er0] = acc[p][0];
            S[(o + 1) * SP + er0] = acc[p][1];
            S[o * SP + er1] = acc[p][2];
            S[(o + 1) * SP + er1] = acc[p][3];
        }
    }
    __syncthreads();
    for (int idx = tid; idx < OUT * 128; idx += 256) {
        int o = idx >> 7;
        int rr = idx & 127;
        float val = S[o * SP + rr];
        if (OUT_NCHW) hout[((row0 >> 12) * OUT + o) * 4096 + (row0 & 4095) + rr] = val;
        else hout[o * N + row0 + rr] = val;
    }
}

// ------------------------------- launch ------------------------------------

extern "C" void kernel_launch(void* const* d_in, const int* in_sizes, int n_in,
                              void* d_out, int out_size) {
    const float* x     = (const float*)d_in[0];
    const float* grid0 = (const float*)d_in[1];
    const float* coef0 = (const float*)d_in[2];
    const float* sb0   = (const float*)d_in[3];
    const float* ss0   = (const float*)d_in[4];
    const float* grid1 = (const float*)d_in[5];
    const float* coef1 = (const float*)d_in[6];
    const float* sb1   = (const float*)d_in[7];
    const float* ss1   = (const float*)d_in[8];
    const float* grid2 = (const float*)d_in[9];
    const float* coef2 = (const float*)d_in[10];
    const float* sb2   = (const float*)d_in[11];
    const float* ss2   = (const float*)d_in[12];
    float* out = (float*)d_out;

    int N = in_sizes[0] / 12;
    if (N > MAXN) N = MAXN;

    float *h1, *h2;
    __nv_bfloat16 *Whi0, *Wlo0, *Whi1, *Wlo1, *Whi2, *Wlo2;
    cudaGetSymbolAddress((void**)&h1, g_h1);
    cudaGetSymbolAddress((void**)&h2, g_h2);
    cudaGetSymbolAddress((void**)&Whi0, g_Whi0);
    cudaGetSymbolAddress((void**)&Wlo0, g_Wlo0);
    cudaGetSymbolAddress((void**)&Whi1, g_Whi1);
    cudaGetSymbolAddress((void**)&Wlo1, g_Wlo1);
    cudaGetSymbolAddress((void**)&Whi2, g_Whi2);
    cudaGetSymbolAddress((void**)&Wlo2, g_Wlo2);

    fold_hilo<<<(64 * 128 + 255) / 256, 256>>>(coef0, sb0, ss0, Whi0, Wlo0, 12, 64, 128);
    fold_hilo<<<(64 * 576 + 255) / 256, 256>>>(coef1, sb1, ss1, Whi1, Wlo1, 64, 64, 576);
    fold_hilo<<<(24 * 576 + 255) / 256, 256>>>(coef2, sb2, ss2, Whi2, Wlo2, 64, 24, 576);

    auto k0 = kan_mma<12, 64, 108, 128, 2, true, false>;
    auto k1 = kan_mma<64, 64, 576, 576, 9, false, false>;
    auto k2 = kan_mma<64, 24, 576, 576, 9, false, true>;

    constexpr int SM01 = 4 * 64 * 256 + 4 * 64 * 128;  // 98304
    constexpr int SM2  = 4 * 64 * 256 + 4 * 24 * 128;  // 77824
    cudaFuncSetAttribute(k0, cudaFuncAttributeMaxDynamicSharedMemorySize, SM01);
    cudaFuncSetAttribute(k1, cudaFuncAttributeMaxDynamicSharedMemorySize, SM01);
    cudaFuncSetAttribute(k2, cudaFuncAttributeMaxDynamicSharedMemorySize, SM2);

    int blocks = N / 128;
    k0<<<blocks, 256, SM01>>>(x, grid0, Whi0, Wlo0, h1, N);
    k1<<<blocks, 256, SM01>>>(h1, grid1, Whi1, Wlo1, h2, N);
    k2<<<blocks, 256, SM2>>>(h2, grid2, Whi2, Wlo2, out, N);
}